// round 6
// baseline (speedup 1.0000x reference)
#include <cuda_runtime.h>
#include <cuda_fp16.h>
#include <math.h>
#include <stdint.h>

#define B_   4
#define L_   512
#define DM   384
#define NL   4
#define DI   768
#define NS   16
#define DTR  24
#define DC   4
#define VOCAB 1544
#define FEAT 1536
#define M_TOK (B_*L_)   // 2048 tokens
#define VPAD 1600       // VOCAB padded to 64-multiple

// ---------------- scratch (no allocations allowed) ----------------
__device__ float g_x[M_TOK*DM];
__device__ float g_xz[M_TOK*2*DI];
__device__ float g_u[M_TOK*DI];
__device__ float g_xdbl[M_TOK*(DTR+2*NS)];   // 56 cols f32 (B,C for scan)

__device__ __half g_ids16[M_TOK*VPAD];
__device__ __half g_fcW16[DM*VPAD];
__device__ __half g_inW16[NL*2*DI*DM];
__device__ __half g_xW16[NL*64*DI];          // N padded 56->64
__device__ __half g_dtW16[NL*DI*64];         // K padded 24->64
__device__ __half g_outW16[NL*DM*DI];
__device__ __half g_headW16[FEAT*DM];
__device__ __half g_h16[M_TOK*DM];
__device__ __half g_y16[M_TOK*DI];
__device__ __half g_xdbl16[M_TOK*64];        // padded 56->64

__device__ __forceinline__ float sigmoidf_(float x){ return 1.f/(1.f+__expf(-x)); }

__device__ __forceinline__ uint32_t smem_u32(const void* p){
    uint32_t a;
    asm("{ .reg .u64 t; cvta.to.shared.u64 t, %1; cvt.u32.u64 %0, t; }" : "=r"(a) : "l"(p));
    return a;
}
__device__ __forceinline__ void cp16(uint32_t s, const void* g){
    asm volatile("cp.async.cg.shared.global [%0],[%1],16;"::"r"(s),"l"(g));
}
__device__ __forceinline__ void cp_commit(){ asm volatile("cp.async.commit_group;"); }
template<int N> __device__ __forceinline__ void cp_wait(){
    asm volatile("cp.async.wait_group %0;"::"n"(N));
}
__device__ __forceinline__ void ldsm_x4(uint32_t&r0,uint32_t&r1,uint32_t&r2,uint32_t&r3,uint32_t a){
    asm volatile("ldmatrix.sync.aligned.m8n8.x4.shared.b16 {%0,%1,%2,%3},[%4];"
        : "=r"(r0),"=r"(r1),"=r"(r2),"=r"(r3) : "r"(a));
}
__device__ __forceinline__ void mma16816(float&c0,float&c1,float&c2,float&c3,
    uint32_t a0,uint32_t a1,uint32_t a2,uint32_t a3,uint32_t b0,uint32_t b1){
    asm volatile("mma.sync.aligned.m16n8k16.row.col.f32.f16.f16.f32 "
        "{%0,%1,%2,%3},{%4,%5,%6,%7},{%8,%9},{%0,%1,%2,%3};"
        : "+f"(c0),"+f"(c1),"+f"(c2),"+f"(c3)
        : "r"(a0),"r"(a1),"r"(a2),"r"(a3),"r"(b0),"r"(b1));
}
__device__ __forceinline__ uint32_t swz(int row, int c16){
    return (uint32_t)(row*128 + (((c16)^(row&7))<<4));
}
__device__ __forceinline__ float softplusf_(float v){
    return fmaxf(v,0.f)+log1pf(__expf(-fabsf(v)));
}

// ============ HMMA f16 GEMM v3 (3-stage cp.async): C = A @ W^T ===============
template<int MW,bool HAS_BIAS,bool SOFTPLUS,bool HAS_RES>
__global__ void __launch_bounds__(256) hgemm2(
    const __half* __restrict__ A, int lda, int nChunks,
    const __half* __restrict__ W, int ldw,
    const float* __restrict__ bias, const float* __restrict__ Res,
    float* __restrict__ C, int Nout)
{
    constexpr int BM = MW*32;
    constexpr int NI = MW;
    constexpr int NWN = 8/MW;
    constexpr int A_STG = BM*64;
    constexpr int B_STG = 64*64;

    extern __shared__ __half smemh[];
    __half* sA = smemh;
    __half* sB = smemh + 3*A_STG;

    const int tid = threadIdx.x;
    const int w   = tid>>5, l = tid&31;
    const int wm  = w / NWN, wn = w % NWN;
    const int m0  = blockIdx.y*BM, n0 = blockIdx.x*64;

    const uint32_t sAb = smem_u32(sA), sBb = smem_u32(sB);
    const __half* Abase = A + (size_t)m0*lda;
    const __half* Wbase = W + (size_t)n0*ldw;

    float acc[2][NI][4];
    #pragma unroll
    for(int i=0;i<2;i++)
        #pragma unroll
        for(int j=0;j<NI;j++)
            #pragma unroll
            for(int q=0;q<4;q++) acc[i][j][q]=0.f;

    auto issue=[&](int c){
        const int st=c%3, k0=c*64;
        const uint32_t sa  = sAb + st*A_STG*2;
        const uint32_t sbp = sBb + st*B_STG*2;
        #pragma unroll
        for(int j=0;j<MW;j++){
            int g=tid+256*j, row=g>>3, c16=g&7;
            cp16(sa + swz(row,c16), Abase + (size_t)row*lda + k0 + c16*8);
        }
        #pragma unroll
        for(int j=0;j<2;j++){
            int g=tid+256*j, row=g>>3, c16=g&7;
            cp16(sbp + swz(row,c16), Wbase + (size_t)row*ldw + k0 + c16*8);
        }
        cp_commit();
    };

    issue(0);
    if(nChunks>1) issue(1);
    for(int c=0;c<nChunks;c++){
        if(c+2<nChunks){ issue(c+2); cp_wait<2>(); }
        else if(c+1<nChunks){ cp_wait<1>(); }
        else { cp_wait<0>(); }
        __syncthreads();
        const int st=c%3;
        const uint32_t aB = sAb + st*A_STG*2;
        const uint32_t bB = sBb + st*B_STG*2;
        #pragma unroll
        for(int ks=0;ks<4;ks++){
            uint32_t af[2][4];
            #pragma unroll
            for(int mi=0;mi<2;mi++){
                int row = wm*32 + mi*16 + (l&15);
                int c16 = ks*2 + (l>>4);
                ldsm_x4(af[mi][0],af[mi][1],af[mi][2],af[mi][3], aB + swz(row,c16));
            }
            uint32_t bf[NI][2];
            #pragma unroll
            for(int np=0;np<NI/2;np++){
                int row = wn*(8*MW) + np*16 + ((l>>4)<<3) + (l&7);
                int c16 = ks*2 + ((l>>3)&1);
                uint32_t r0,r1,r2,r3;
                ldsm_x4(r0,r1,r2,r3, bB + swz(row,c16));
                bf[np*2][0]=r0; bf[np*2][1]=r1; bf[np*2+1][0]=r2; bf[np*2+1][1]=r3;
            }
            #pragma unroll
            for(int mi=0;mi<2;mi++)
                #pragma unroll
                for(int ni=0;ni<NI;ni++)
                    mma16816(acc[mi][ni][0],acc[mi][ni][1],acc[mi][ni][2],acc[mi][ni][3],
                             af[mi][0],af[mi][1],af[mi][2],af[mi][3],
                             bf[ni][0],bf[ni][1]);
        }
        __syncthreads();
    }

    const int grp=l>>2, tig=l&3;
    #pragma unroll
    for(int mi=0;mi<2;mi++){
        int gm0 = m0 + wm*32 + mi*16 + grp;
        #pragma unroll
        for(int ni=0;ni<NI;ni++){
            int gn = n0 + wn*(8*MW) + ni*8 + tig*2;
            #pragma unroll
            for(int half=0; half<2; half++){
                int gm = gm0 + half*8;
                float v0=acc[mi][ni][half*2], v1=acc[mi][ni][half*2+1];
                if(gn<Nout){
                    if(HAS_BIAS){ v0+=bias[gn]; v1+=bias[gn+1]; }
                    if(SOFTPLUS){ v0=softplusf_(v0); v1=softplusf_(v1); }
                    if(HAS_RES){
                        v0 += Res[(size_t)gm*Nout+gn];
                        v1 += Res[(size_t)gm*Nout+gn+1];
                    }
                    C[(size_t)gm*Nout+gn]   = v0;
                    C[(size_t)gm*Nout+gn+1] = v1;
                }
            }
        }
    }
}

// ============ fused conv+SiLU + x_proj GEMM ==================================
// BM=64, N=64 (56 valid). grid (1, 32). Computes u from xz on the fly,
// writes u f32 (for scan), xdbl f32 (B,C) and xdbl16 (padded, for delta).
__global__ void __launch_bounds__(256) xproj_k(
    const float* __restrict__ xz, const float* __restrict__ cw,
    const float* __restrict__ cb, const __half* __restrict__ W,
    float* __restrict__ u_out, float* __restrict__ xdbl, __half* __restrict__ xdbl16)
{
    __shared__ __half sA[64*64];
    __shared__ __half sW[2][64*64];
    __shared__ float scw[64*4];
    __shared__ float scb[64];

    const int tid = threadIdx.x;
    const int w   = tid>>5, l = tid&31;
    const int wm  = w>>2, wn = w&3;         // MW=2 layout: 2 x 4 warps
    const int m0  = blockIdx.y*64;

    const uint32_t sAb = smem_u32(sA), sWb = smem_u32(sW);

    float acc[2][2][4];
    #pragma unroll
    for(int i=0;i<2;i++)
        #pragma unroll
        for(int j=0;j<2;j++)
            #pragma unroll
            for(int q=0;q<4;q++) acc[i][j][q]=0.f;

    auto issueW=[&](int c){
        const int st=c&1, k0=c*64;
        const uint32_t sp = sWb + st*(64*64*2);
        #pragma unroll
        for(int j=0;j<2;j++){
            int g=tid+256*j, row=g>>3, c16=g&7;
            cp16(sp + swz(row,c16), W + (size_t)row*DI + k0 + c16*8);
        }
        cp_commit();
    };

    issueW(0);
    for(int c=0;c<12;c++){
        __syncthreads();                    // prior MMA done: sA, scw, sW[(c+1)&1] free
        if(c+1<12) issueW(c+1);
        const int k0=c*64;
        if(tid<256){
            if(tid<256){
                // conv weights for this channel chunk
                if(tid<64*4) scw[tid]=cw[(size_t)(k0+(tid>>2))*4 + (tid&3)];
                if(tid>=192 && tid<256) scb[tid-192]=cb[k0+tid-192];
            }
        }
        __syncthreads();                    // scw/scb visible
        // compute u for 64 rows x 64 channels
        #pragma unroll 4
        for(int idx=tid; idx<4096; idx+=256){
            int r=idx>>6, d=idx&63;
            int row=m0+r, ll=row&(L_-1);
            float a=scb[d];
            #pragma unroll
            for(int j=0;j<DC;j++){
                int ls=ll-(DC-1)+j;
                if(ls>=0) a=fmaf(xz[(size_t)(row-(DC-1)+j)*(2*DI) + k0+d], scw[d*4+j], a);
            }
            float uv=a*sigmoidf_(a);
            u_out[(size_t)row*DI + k0+d]=uv;
            *(__half*)((char*)sA + swz(r, d>>3) + (d&7)*2) = __float2half(uv);
        }
        cp_wait<1>();                       // W chunk c resident (c+1 may be in flight)
        __syncthreads();                    // sA + sW visible to all
        const uint32_t bB = sWb + (c&1)*(64*64*2);
        #pragma unroll
        for(int ks=0;ks<4;ks++){
            uint32_t af[2][4];
            #pragma unroll
            for(int mi=0;mi<2;mi++){
                int row = wm*32 + mi*16 + (l&15);
                int c16 = ks*2 + (l>>4);
                ldsm_x4(af[mi][0],af[mi][1],af[mi][2],af[mi][3], sAb + swz(row,c16));
            }
            uint32_t bf[2][2];
            {
                int row = wn*16 + ((l>>4)<<3) + (l&7);
                int c16 = ks*2 + ((l>>3)&1);
                uint32_t r0,r1,r2,r3;
                ldsm_x4(r0,r1,r2,r3, bB + swz(row,c16));
                bf[0][0]=r0; bf[0][1]=r1; bf[1][0]=r2; bf[1][1]=r3;
            }
            #pragma unroll
            for(int mi=0;mi<2;mi++)
                #pragma unroll
                for(int ni=0;ni<2;ni++)
                    mma16816(acc[mi][ni][0],acc[mi][ni][1],acc[mi][ni][2],acc[mi][ni][3],
                             af[mi][0],af[mi][1],af[mi][2],af[mi][3],
                             bf[ni][0],bf[ni][1]);
        }
    }

    const int grp=l>>2, tig=l&3;
    #pragma unroll
    for(int mi=0;mi<2;mi++){
        int gm0 = m0 + wm*32 + mi*16 + grp;
        #pragma unroll
        for(int ni=0;ni<2;ni++){
            int gn = wn*16 + ni*8 + tig*2;
            #pragma unroll
            for(int half=0; half<2; half++){
                int gm = gm0 + half*8;
                float v0=acc[mi][ni][half*2], v1=acc[mi][ni][half*2+1];
                if(gn<DTR+2*NS){            // both gn,gn+1 < 56 (gn even)
                    xdbl[(size_t)gm*(DTR+2*NS)+gn]   = v0;
                    xdbl[(size_t)gm*(DTR+2*NS)+gn+1] = v1;
                }
                __half2 hv=__floats2half2_rn(v0,v1);   // cols>=56 are 0 (padded W)
                *(__half2*)(xdbl16 + (size_t)gm*64 + gn) = hv;
            }
        }
    }
}

// ---------------- merged weight/input conversion ------------------
#define CR0 (M_TOK*VPAD)
#define CR1 (CR0 + DM*VPAD)
#define CR2 (CR1 + NL*2*DI*DM)
#define CR3 (CR2 + NL*64*DI)
#define CR4 (CR3 + NL*DI*64)
#define CR5 (CR4 + NL*DM*DI)
#define CR6 (CR5 + FEAT*DM)
__global__ __launch_bounds__(256) void cvt_all_k(
    const float* __restrict__ ids, const float* __restrict__ fcW,
    const float* __restrict__ inW, const float* __restrict__ xW,
    const float* __restrict__ dtW, const float* __restrict__ outW,
    const float* __restrict__ headW,
    __half* __restrict__ d_ids, __half* __restrict__ d_fcW,
    __half* __restrict__ d_inW, __half* __restrict__ d_xW,
    __half* __restrict__ d_dtW, __half* __restrict__ d_outW,
    __half* __restrict__ d_headW)
{
    int i=blockIdx.x*256+threadIdx.x;
    if(i<CR0){
        int r=i/VPAD, c=i%VPAD;
        d_ids[i]=__float2half(c<VOCAB ? ids[(size_t)r*VOCAB+c] : 0.f);
    } else if(i<CR1){
        int j=i-CR0, r=j/VPAD, c=j%VPAD;
        d_fcW[j]=__float2half(c<VOCAB ? fcW[(size_t)r*VOCAB+c] : 0.f);
    } else if(i<CR2){
        int j=i-CR1;
        d_inW[j]=__float2half(inW[j]);
    } else if(i<CR3){
        int j=i-CR2, lay=j/(64*DI), rem=j%(64*DI), r=rem/DI, cc=rem%DI;
        d_xW[j]=__float2half(r<DTR+2*NS ? xW[((size_t)lay*(DTR+2*NS)+r)*DI+cc] : 0.f);
    } else if(i<CR4){
        int j=i-CR3, row=j/64, c=j%64;
        d_dtW[j]=__float2half(c<DTR ? dtW[(size_t)row*DTR+c] : 0.f);
    } else if(i<CR5){
        int j=i-CR4;
        d_outW[j]=__float2half(outW[j]);
    } else if(i<CR6){
        int j=i-CR5;
        d_headW[j]=__float2half(headW[j]);
    }
}

// ---------------- RMSNorm -> f16 ----------------------------------
__global__ __launch_bounds__(128) void rmsnorm_k(
    const float* __restrict__ x, const float* __restrict__ w, __half* __restrict__ o)
{
    const int row=blockIdx.x, tid=threadIdx.x;
    float s=0.f;
    for(int c=tid;c<DM;c+=128){ float v=x[(size_t)row*DM+c]; s+=v*v; }
    #pragma unroll
    for(int off=16;off;off>>=1) s+=__shfl_xor_sync(0xffffffffu,s,off);
    __shared__ float ws[4];
    if((tid&31)==0) ws[tid>>5]=s;
    __syncthreads();
    if(tid<32){
        float t=(tid<4)?ws[tid]:0.f;
        t+=__shfl_xor_sync(0xffffffffu,t,1);
        t+=__shfl_xor_sync(0xffffffffu,t,2);
        if(tid==0) ws[0]=t;
    }
    __syncthreads();
    const float rms=rsqrtf(ws[0]/(float)DM + 1e-5f);
    for(int c=tid;c<DM;c+=128)
        o[(size_t)row*DM+c]=__float2half(x[(size_t)row*DM+c]*rms*w[c]);
}

// ---------------- scan (delta GEMM + softplus fused in) -----------
__global__ __launch_bounds__(128) void scan2_k(
    const __half* __restrict__ xdbl16, const __half* __restrict__ dtW16,
    const float* __restrict__ dtb,
    const float* __restrict__ u, const float* __restrict__ xdbl,
    const float* __restrict__ xz,
    const float* __restrict__ Alog, const float* __restrict__ Dv,
    __half* __restrict__ y)
{
    constexpr int CL=64, CPB=32;
    __shared__ float sB[CL][NS], sC[CL][NS];
    __shared__ float sd[CL][CPB], su[CL][CPB], sr[CL][CPB];
    __shared__ uint32_t sXd[CL][12];
    __shared__ __half sDtW[CPB][24];
    __shared__ float sdtb[CPB];

    const int b=blockIdx.y, ch0=blockIdx.x*CPB;
    const int tid=threadIdx.x, chl=tid>>2, sub=tid&3, ch=ch0+chl;

    for(int i=tid;i<CPB*24;i+=128) sDtW[i/24][i%24]=dtW16[(size_t)(ch0+i/24)*64 + i%24];
    if(tid<CPB) sdtb[tid]=dtb[ch0+tid];

    float a[4];
    #pragma unroll
    for(int j=0;j<4;j++) a[j]=-__expf(Alog[ch*NS + sub*4 + j]);
    const float Dd=Dv[ch];
    float h[4]={0.f,0.f,0.f,0.f};
    const int base=b*L_;

    for(int l0=0;l0<L_;l0+=CL){
        for(int i=tid;i<CL*32;i+=128){
            int s=i>>5, c=i&31;
            float v=xdbl[(size_t)(base+l0+s)*(DTR+2*NS) + DTR + c];
            if(c<NS) sB[s][c]=v; else sC[s][c-NS]=v;
        }
        for(int i=tid;i<CL*12;i+=128){
            int s=i/12, p=i%12;
            sXd[s][p]=((const uint32_t*)(xdbl16+(size_t)(base+l0+s)*64))[p];
        }
        for(int i=tid;i<CL*CPB;i+=128){
            int s=i/CPB, c=i%CPB;
            size_t row=(size_t)(base+l0+s);
            su[s][c]=u[row*DI+ch0+c];
            sr[s][c]=xz[row*(2*DI)+DI+ch0+c];
        }
        __syncthreads();
        // delta = softplus(xdbl16[:, :24] @ dtW^T + b)
        for(int i=tid;i<CL*CPB;i+=128){
            int s=i>>5, c=i&31;
            float acc2=sdtb[c];
            #pragma unroll
            for(int p=0;p<12;p++){
                float2 xv=__half22float2(*(const __half2*)&sXd[s][p]);
                float2 wv=__half22float2(*(const __half2*)&sDtW[c][p*2]);
                acc2 = fmaf(xv.x,wv.x,fmaf(xv.y,wv.y,acc2));
            }
            sd[s][c]=softplusf_(acc2);
        }
        __syncthreads();
        #pragma unroll 4
        for(int s=0;s<CL;s++){
            float dt=sd[s][chl], ut=su[s][chl];
            float du=dt*ut;
            float acc2=0.f;
            #pragma unroll
            for(int j=0;j<4;j++){
                float dA=__expf(dt*a[j]);
                h[j]=fmaf(dA,h[j], du*sB[s][sub*4+j]);
                acc2=fmaf(h[j], sC[s][sub*4+j], acc2);
            }
            acc2+=__shfl_xor_sync(0xffffffffu,acc2,1);
            acc2+=__shfl_xor_sync(0xffffffffu,acc2,2);
            if(sub==0){
                float r=sr[s][chl];
                y[(size_t)(base+l0+s)*DI+ch]=__float2half((acc2+ut*Dd)*(r*sigmoidf_(r)));
            }
        }
        __syncthreads();
    }
}

// ---------------- host launcher -----------------------------------
extern "C" void kernel_launch(void* const* d_in, const int* in_sizes, int n_in,
                              void* d_out, int out_size)
{
    const float* input_ids = (const float*)d_in[0];
    const float* fc_W      = (const float*)d_in[1];
    const float* fc_b      = (const float*)d_in[2];
    const float* in_proj_W = (const float*)d_in[3];
    const float* conv_W    = (const float*)d_in[4];
    const float* conv_b    = (const float*)d_in[5];
    const float* x_proj_W  = (const float*)d_in[6];
    const float* dt_proj_W = (const float*)d_in[7];
    const float* dt_proj_b = (const float*)d_in[8];
    const float* A_log     = (const float*)d_in[9];
    const float* Dv        = (const float*)d_in[10];
    const float* out_proj_W= (const float*)d_in[11];
    const float* norm_W    = (const float*)d_in[12];
    const float* normf_W   = (const float*)d_in[13];
    const float* head_W    = (const float*)d_in[14];
    float* out = (float*)d_out;

    float *x,*xz,*u,*xdbl;
    __half *ids16,*fcW16,*inW16,*xW16,*dtW16,*outW16,*headW16,*h16,*y16,*xdbl16;
    cudaGetSymbolAddress((void**)&x,      g_x);
    cudaGetSymbolAddress((void**)&xz,     g_xz);
    cudaGetSymbolAddress((void**)&u,      g_u);
    cudaGetSymbolAddress((void**)&xdbl,   g_xdbl);
    cudaGetSymbolAddress((void**)&ids16,  g_ids16);
    cudaGetSymbolAddress((void**)&fcW16,  g_fcW16);
    cudaGetSymbolAddress((void**)&inW16,  g_inW16);
    cudaGetSymbolAddress((void**)&xW16,   g_xW16);
    cudaGetSymbolAddress((void**)&dtW16,  g_dtW16);
    cudaGetSymbolAddress((void**)&outW16, g_outW16);
    cudaGetSymbolAddress((void**)&headW16,g_headW16);
    cudaGetSymbolAddress((void**)&h16,    g_h16);
    cudaGetSymbolAddress((void**)&y16,    g_y16);
    cudaGetSymbolAddress((void**)&xdbl16, g_xdbl16);

    const int SM2 = 3*(64*64  + 64*64)*2;   // 49152
    const int SM4 = 3*(128*64 + 64*64)*2;   // 73728
    cudaFuncSetAttribute(hgemm2<2,true ,false,false>, cudaFuncAttributeMaxDynamicSharedMemorySize, SM2);
    cudaFuncSetAttribute(hgemm2<2,false,false,true >, cudaFuncAttributeMaxDynamicSharedMemorySize, SM2);
    cudaFuncSetAttribute(hgemm2<4,false,false,false>, cudaFuncAttributeMaxDynamicSharedMemorySize, SM4);

    // 1. all conversions in one kernel
    cvt_all_k<<<(CR6+255)/256,256>>>(input_ids, fc_W, in_proj_W, x_proj_W,
        dt_proj_W, out_proj_W, head_W,
        ids16, fcW16, inW16, xW16, dtW16, outW16, headW16);

    // 2. fc: x = ids @ fc_W^T + b  (K=1600, 25 chunks)
    hgemm2<2,true,false,false><<<dim3(6,32),256,SM2>>>(
        ids16, VPAD, 25, fcW16, VPAD, fc_b, nullptr, x, DM);

    for(int i=0;i<NL;i++){
        rmsnorm_k<<<M_TOK,128>>>(x, norm_W+(size_t)i*DM, h16);
        hgemm2<4,false,false,false><<<dim3(24,16),256,SM4>>>(
            h16, DM, 6, inW16+(size_t)i*2*DI*DM, DM, nullptr, nullptr, xz, 2*DI);
        xproj_k<<<dim3(1,32),256>>>(
            xz, conv_W+(size_t)i*DI*DC, conv_b+(size_t)i*DI,
            xW16+(size_t)i*64*DI, u, xdbl, xdbl16);
        scan2_k<<<dim3(DI/32, B_),128>>>(
            xdbl16, dtW16+(size_t)i*DI*64, dt_proj_b+(size_t)i*DI,
            u, xdbl, xz, A_log+(size_t)i*DI*NS, Dv+(size_t)i*DI, y16);
        hgemm2<2,false,false,true><<<dim3(6,32),256,SM2>>>(
            y16, DI, 12, outW16+(size_t)i*DM*DI, DI, nullptr, x, x, DM);
    }

    rmsnorm_k<<<M_TOK,128>>>(x, normf_W, h16);
    hgemm2<4,false,false,false><<<dim3(24,16),256,SM4>>>(
        h16, DM, 6, headW16, DM, nullptr, nullptr, out, FEAT);
}

// round 7
// speedup vs baseline: 1.3680x; 1.3680x over previous
#include <cuda_runtime.h>
#include <cuda_fp16.h>
#include <math.h>
#include <stdint.h>

#define B_   4
#define L_   512
#define DM   384
#define NL   4
#define DI   768
#define NS   16
#define DTR  24
#define DC   4
#define VOCAB 1544
#define FEAT 1536
#define M_TOK (B_*L_)   // 2048 tokens
#define VPAD 1600

// ---------------- scratch (no allocations allowed) ----------------
__device__ float g_x[M_TOK*DM];
__device__ float g_xz[M_TOK*2*DI];
__device__ float g_u[M_TOK*DI];
__device__ float g_xdbl[M_TOK*(DTR+2*NS)];
__device__ float g_delta[M_TOK*DI];

__device__ __half g_ids16[M_TOK*VPAD];
__device__ __half g_fcW16[DM*VPAD];
__device__ __half g_inW16[NL*2*DI*DM];
__device__ __half g_xW16[NL*64*DI];
__device__ __half g_dtW16[NL*DI*64];
__device__ __half g_outW16[NL*DM*DI];
__device__ __half g_headW16[FEAT*DM];
__device__ __half g_h16[M_TOK*DM];
__device__ __half g_u16[M_TOK*DI];
__device__ __half g_y16[M_TOK*DI];
__device__ __half g_xdbl16[M_TOK*64];

// ---------------- grid barrier ------------------------------------
__device__ unsigned g_cnt;
__device__ volatile unsigned g_gen;

__device__ __forceinline__ void grid_bar(){
    __syncthreads();
    if(threadIdx.x==0){
        unsigned g=g_gen;
        __threadfence();
        if(atomicAdd(&g_cnt,1)==gridDim.x-1){
            g_cnt=0;
            __threadfence();
            g_gen=g+1;
        } else {
            while(g_gen==g){}
        }
        __threadfence();
    }
    __syncthreads();
}

__device__ __forceinline__ float sigmoidf_(float x){ return 1.f/(1.f+__expf(-x)); }
__device__ __forceinline__ float softplusf_(float v){
    return fmaxf(v,0.f)+log1pf(__expf(-fabsf(v)));
}
__device__ __forceinline__ uint32_t smem_u32(const void* p){
    uint32_t a;
    asm("{ .reg .u64 t; cvta.to.shared.u64 t, %1; cvt.u32.u64 %0, t; }" : "=r"(a) : "l"(p));
    return a;
}
__device__ __forceinline__ void cp16(uint32_t s, const void* g){
    asm volatile("cp.async.cg.shared.global [%0],[%1],16;"::"r"(s),"l"(g));
}
__device__ __forceinline__ void cp_commit(){ asm volatile("cp.async.commit_group;"); }
template<int N> __device__ __forceinline__ void cp_wait(){
    asm volatile("cp.async.wait_group %0;"::"n"(N));
}
__device__ __forceinline__ void ldsm_x4(uint32_t&r0,uint32_t&r1,uint32_t&r2,uint32_t&r3,uint32_t a){
    asm volatile("ldmatrix.sync.aligned.m8n8.x4.shared.b16 {%0,%1,%2,%3},[%4];"
        : "=r"(r0),"=r"(r1),"=r"(r2),"=r"(r3) : "r"(a));
}
__device__ __forceinline__ void mma16816(float&c0,float&c1,float&c2,float&c3,
    uint32_t a0,uint32_t a1,uint32_t a2,uint32_t a3,uint32_t b0,uint32_t b1){
    asm volatile("mma.sync.aligned.m16n8k16.row.col.f32.f16.f16.f32 "
        "{%0,%1,%2,%3},{%4,%5,%6,%7},{%8,%9},{%0,%1,%2,%3};"
        : "+f"(c0),"+f"(c1),"+f"(c2),"+f"(c3)
        : "r"(a0),"r"(a1),"r"(a2),"r"(a3),"r"(b0),"r"(b1));
}
__device__ __forceinline__ uint32_t swz(int row, int c16){
    return (uint32_t)(row*128 + (((c16)^(row&7))<<4));
}

// ============ GEMM phase: BM=128,BN=64,BK=64, 3-stage cp.async ===============
template<bool HAS_BIAS,bool SOFTPLUS,bool HAS_RES,bool WF16>
__device__ __noinline__ void gemm_phase(char* smemc, int nTx, int nTy,
    const __half* __restrict__ A, int lda, int nChunks,
    const __half* __restrict__ W, int ldw,
    const float* __restrict__ bias, const float* __restrict__ Res,
    float* __restrict__ C, int Nout, __half* __restrict__ C16, int ld16)
{
    constexpr int A_STG = 128*64;
    constexpr int B_STG = 64*64;
    __half* sA=(__half*)smemc;
    __half* sB=sA+3*A_STG;
    const int tid=threadIdx.x, w=tid>>5, l=tid&31;
    const int wm=w>>1, wn=w&1;
    const uint32_t sAb=smem_u32(sA), sBb=smem_u32(sB);

    for(int t=blockIdx.x; t<nTx*nTy; t+=gridDim.x){
        const int m0=(t/nTx)*128, n0=(t%nTx)*64;
        const __half* Abase=A+(size_t)m0*lda;
        const __half* Wbase=W+(size_t)n0*ldw;

        float acc[2][4][4];
        #pragma unroll
        for(int i=0;i<2;i++)
            #pragma unroll
            for(int j=0;j<4;j++)
                #pragma unroll
                for(int q=0;q<4;q++) acc[i][j][q]=0.f;

        auto issue=[&](int c){
            const int st=c%3, k0=c*64;
            const uint32_t sa  = sAb + st*A_STG*2;
            const uint32_t sbp = sBb + st*B_STG*2;
            #pragma unroll
            for(int j=0;j<4;j++){
                int g=tid+256*j, row=g>>3, c16=g&7;
                cp16(sa + swz(row,c16), Abase + (size_t)row*lda + k0 + c16*8);
            }
            #pragma unroll
            for(int j=0;j<2;j++){
                int g=tid+256*j, row=g>>3, c16=g&7;
                cp16(sbp + swz(row,c16), Wbase + (size_t)row*ldw + k0 + c16*8);
            }
            cp_commit();
        };

        issue(0);
        if(nChunks>1) issue(1);
        for(int c=0;c<nChunks;c++){
            if(c+2<nChunks){ issue(c+2); cp_wait<2>(); }
            else if(c+1<nChunks){ cp_wait<1>(); }
            else { cp_wait<0>(); }
            __syncthreads();
            const int st=c%3;
            const uint32_t aB = sAb + st*A_STG*2;
            const uint32_t bB = sBb + st*B_STG*2;
            #pragma unroll
            for(int ks=0;ks<4;ks++){
                uint32_t af[2][4];
                #pragma unroll
                for(int mi=0;mi<2;mi++){
                    int row = wm*32 + mi*16 + (l&15);
                    int c16 = ks*2 + (l>>4);
                    ldsm_x4(af[mi][0],af[mi][1],af[mi][2],af[mi][3], aB + swz(row,c16));
                }
                uint32_t bf[4][2];
                #pragma unroll
                for(int np=0;np<2;np++){
                    int row = wn*32 + np*16 + ((l>>4)<<3) + (l&7);
                    int c16 = ks*2 + ((l>>3)&1);
                    uint32_t r0,r1,r2,r3;
                    ldsm_x4(r0,r1,r2,r3, bB + swz(row,c16));
                    bf[np*2][0]=r0; bf[np*2][1]=r1; bf[np*2+1][0]=r2; bf[np*2+1][1]=r3;
                }
                #pragma unroll
                for(int mi=0;mi<2;mi++)
                    #pragma unroll
                    for(int ni=0;ni<4;ni++)
                        mma16816(acc[mi][ni][0],acc[mi][ni][1],acc[mi][ni][2],acc[mi][ni][3],
                                 af[mi][0],af[mi][1],af[mi][2],af[mi][3],
                                 bf[ni][0],bf[ni][1]);
            }
            __syncthreads();
        }

        const int grp=l>>2, tig=l&3;
        #pragma unroll
        for(int mi=0;mi<2;mi++){
            int gm0 = m0 + wm*32 + mi*16 + grp;
            #pragma unroll
            for(int ni=0;ni<4;ni++){
                int gn = n0 + wn*32 + ni*8 + tig*2;
                #pragma unroll
                for(int half=0; half<2; half++){
                    int gm = gm0 + half*8;
                    float v0=acc[mi][ni][half*2], v1=acc[mi][ni][half*2+1];
                    if(gn<Nout){
                        if(HAS_BIAS){ v0+=bias[gn]; v1+=bias[gn+1]; }
                        if(SOFTPLUS){ v0=softplusf_(v0); v1=softplusf_(v1); }
                        if(HAS_RES){
                            v0 += Res[(size_t)gm*Nout+gn];
                            v1 += Res[(size_t)gm*Nout+gn+1];
                        }
                        C[(size_t)gm*Nout+gn]   = v0;
                        C[(size_t)gm*Nout+gn+1] = v1;
                    }
                    if(WF16){
                        if(gn<ld16){
                            __half2 hv=__floats2half2_rn(gn<Nout?v0:0.f, gn+1<Nout?v1:0.f);
                            *(__half2*)(C16 + (size_t)gm*ld16 + gn)=hv;
                        }
                    }
                }
            }
        }
    }
}

// ============ conversion phase ===============================================
#define CR0 (M_TOK*VPAD)
#define CR1 (CR0 + DM*VPAD)
#define CR2 (CR1 + NL*2*DI*DM)
#define CR3 (CR2 + NL*64*DI)
#define CR4 (CR3 + NL*DI*64)
#define CR5 (CR4 + NL*DM*DI)
#define CR6 (CR5 + FEAT*DM)
__device__ __noinline__ void cvt_phase(
    const float* __restrict__ ids, const float* __restrict__ fcW,
    const float* __restrict__ inW, const float* __restrict__ xW,
    const float* __restrict__ dtW, const float* __restrict__ outW,
    const float* __restrict__ headW)
{
    const int stride=gridDim.x*256;
    for(int i=blockIdx.x*256+threadIdx.x; i<CR6; i+=stride){
        if(i<CR0){
            int r=i/VPAD, c=i%VPAD;
            g_ids16[i]=__float2half(c<VOCAB ? ids[(size_t)r*VOCAB+c] : 0.f);
        } else if(i<CR1){
            int j=i-CR0, r=j/VPAD, c=j%VPAD;
            g_fcW16[j]=__float2half(c<VOCAB ? fcW[(size_t)r*VOCAB+c] : 0.f);
        } else if(i<CR2){
            int j=i-CR1;
            g_inW16[j]=__float2half(inW[j]);
        } else if(i<CR3){
            int j=i-CR2, lay=j/(64*DI), rem=j%(64*DI), r=rem/DI, cc=rem%DI;
            g_xW16[j]=__float2half(r<DTR+2*NS ? xW[((size_t)lay*(DTR+2*NS)+r)*DI+cc] : 0.f);
        } else if(i<CR4){
            int j=i-CR3, row=j/64, c=j%64;
            g_dtW16[j]=__float2half(c<DTR ? dtW[(size_t)row*DTR+c] : 0.f);
        } else if(i<CR5){
            g_outW16[i-CR4]=__float2half(outW[i-CR4]);
        } else {
            g_headW16[i-CR5]=__float2half(headW[i-CR5]);
        }
    }
}

// ============ rmsnorm phase (warp per row) ===================================
__device__ __noinline__ void rms_phase(
    const float* __restrict__ x, const float* __restrict__ w, __half* __restrict__ o)
{
    const int lane=threadIdx.x&31;
    const int gw = blockIdx.x*8 + (threadIdx.x>>5);
    for(int row=gw; row<M_TOK; row+=gridDim.x*8){
        float s=0.f, v[12];
        #pragma unroll
        for(int j=0;j<12;j++){ v[j]=x[(size_t)row*DM + lane + 32*j]; s+=v[j]*v[j]; }
        #pragma unroll
        for(int off=16;off;off>>=1) s+=__shfl_xor_sync(0xffffffffu,s,off);
        const float rms=rsqrtf(s/(float)DM + 1e-5f);
        #pragma unroll
        for(int j=0;j<12;j++)
            o[(size_t)row*DM + lane + 32*j]=__float2half(v[j]*rms*w[lane+32*j]);
    }
}

// ============ conv + SiLU phase ==============================================
__device__ __noinline__ void conv_phase(
    const float* __restrict__ xz, const float* __restrict__ cw,
    const float* __restrict__ cb, float* __restrict__ u, __half* __restrict__ u16)
{
    const int stride=gridDim.x*256;
    for(int idx=blockIdx.x*256+threadIdx.x; idx<M_TOK*DI; idx+=stride){
        int d=idx%DI, m=idx/DI, l=m%L_;
        float acc=cb[d];
        #pragma unroll
        for(int j=0;j<DC;j++){
            int ls=l-(DC-1)+j;
            if(ls>=0) acc=fmaf(xz[(size_t)(m-(DC-1)+j)*(2*DI)+d], cw[d*DC+j], acc);
        }
        float v=acc*sigmoidf_(acc);
        u[idx]=v;
        u16[idx]=__float2half(v);
    }
}

// ============ scan phase (256 thr: 64 channels/tile, 48 tiles) ===============
struct ScanSmem {
    float B[64][NS]; float C[64][NS];
    float d[64][64]; float u[64][64]; float r[64][64];
};
__device__ __noinline__ void scan_phase(char* smemc,
    const float* __restrict__ delta, const float* __restrict__ uu,
    const float* __restrict__ xdbl,  const float* __restrict__ xz,
    const float* __restrict__ Alog,  const float* __restrict__ Dv,
    __half* __restrict__ y)
{
    ScanSmem& sh = *(ScanSmem*)smemc;
    const int tid=threadIdx.x, chl=tid>>2, sub=tid&3;

    for(int t=blockIdx.x; t<48; t+=gridDim.x){
        const int b=t/12, ch0=(t%12)*64, ch=ch0+chl;
        float a[4];
        #pragma unroll
        for(int j=0;j<4;j++) a[j]=-__expf(Alog[ch*NS + sub*4 + j]);
        const float Dd=Dv[ch];
        float h[4]={0.f,0.f,0.f,0.f};
        const int base=b*L_;

        for(int l0=0;l0<L_;l0+=64){
            for(int i=tid;i<64*32;i+=256){
                int s=i>>5, c=i&31;
                float v=xdbl[(size_t)(base+l0+s)*(DTR+2*NS) + DTR + c];
                if(c<NS) sh.B[s][c]=v; else sh.C[s][c-NS]=v;
            }
            for(int i=tid;i<64*64;i+=256){
                int s=i>>6, c=i&63;
                size_t row=(size_t)(base+l0+s);
                sh.d[s][c]=delta[row*DI+ch0+c];
                sh.u[s][c]=uu[row*DI+ch0+c];
                sh.r[s][c]=xz[row*(2*DI)+DI+ch0+c];
            }
            __syncthreads();
            #pragma unroll 4
            for(int s=0;s<64;s++){
                float dt=sh.d[s][chl], ut=sh.u[s][chl];
                float du=dt*ut;
                float acc=0.f;
                #pragma unroll
                for(int j=0;j<4;j++){
                    float dA=__expf(dt*a[j]);
                    h[j]=fmaf(dA,h[j], du*sh.B[s][sub*4+j]);
                    acc=fmaf(h[j], sh.C[s][sub*4+j], acc);
                }
                acc+=__shfl_xor_sync(0xffffffffu,acc,1);
                acc+=__shfl_xor_sync(0xffffffffu,acc,2);
                if(sub==0){
                    float r=sh.r[s][chl];
                    y[(size_t)(base+l0+s)*DI+ch]=__float2half((acc+ut*Dd)*(r*sigmoidf_(r)));
                }
            }
            __syncthreads();
        }
    }
}

// ============ the mega-kernel ================================================
__global__ __launch_bounds__(256) void mega_k(
    const float* ids, const float* fcW, const float* fcb, const float* inW,
    const float* cw, const float* cb, const float* xW, const float* dtW,
    const float* dtb, const float* Alog, const float* Dv, const float* outW,
    const float* normW, const float* normfW, const float* headW, float* out)
{
    extern __shared__ char smemc[];

    cvt_phase(ids,fcW,inW,xW,dtW,outW,headW);
    grid_bar();

    gemm_phase<true,false,false,false>(smemc,6,16, g_ids16,VPAD,25, g_fcW16,VPAD,
        fcb,nullptr, g_x,DM, nullptr,0);
    grid_bar();

    for(int i=0;i<NL;i++){
        rms_phase(g_x, normW+(size_t)i*DM, g_h16);
        grid_bar();
        gemm_phase<false,false,false,false>(smemc,24,16, g_h16,DM,6,
            g_inW16+(size_t)i*2*DI*DM,DM, nullptr,nullptr, g_xz,2*DI, nullptr,0);
        grid_bar();
        conv_phase(g_xz, cw+(size_t)i*DI*DC, cb+(size_t)i*DI, g_u, g_u16);
        grid_bar();
        gemm_phase<false,false,false,true>(smemc,1,16, g_u16,DI,12,
            g_xW16+(size_t)i*64*DI,DI, nullptr,nullptr, g_xdbl,DTR+2*NS, g_xdbl16,64);
        grid_bar();
        gemm_phase<true,true,false,false>(smemc,12,16, g_xdbl16,64,1,
            g_dtW16+(size_t)i*DI*64,64, dtb+(size_t)i*DI,nullptr, g_delta,DI, nullptr,0);
        grid_bar();
        scan_phase(smemc, g_delta, g_u, g_xdbl, g_xz,
            Alog+(size_t)i*DI*NS, Dv+(size_t)i*DI, g_y16);
        grid_bar();
        gemm_phase<false,false,true,false>(smemc,6,16, g_y16,DI,12,
            g_outW16+(size_t)i*DM*DI,DI, nullptr,g_x, g_x,DM, nullptr,0);
        grid_bar();
    }

    rms_phase(g_x, normfW, g_h16);
    grid_bar();
    gemm_phase<false,false,false,false>(smemc,24,16, g_h16,DM,6, g_headW16,DM,
        nullptr,nullptr, out,FEAT, nullptr,0);
}

// ---------------- host launcher -----------------------------------
extern "C" void kernel_launch(void* const* d_in, const int* in_sizes, int n_in,
                              void* d_out, int out_size)
{
    const float* input_ids = (const float*)d_in[0];
    const float* fc_W      = (const float*)d_in[1];
    const float* fc_b      = (const float*)d_in[2];
    const float* in_proj_W = (const float*)d_in[3];
    const float* conv_W    = (const float*)d_in[4];
    const float* conv_b    = (const float*)d_in[5];
    const float* x_proj_W  = (const float*)d_in[6];
    const float* dt_proj_W = (const float*)d_in[7];
    const float* dt_proj_b = (const float*)d_in[8];
    const float* A_log     = (const float*)d_in[9];
    const float* Dv        = (const float*)d_in[10];
    const float* out_proj_W= (const float*)d_in[11];
    const float* norm_W    = (const float*)d_in[12];
    const float* normf_W   = (const float*)d_in[13];
    const float* head_W    = (const float*)d_in[14];
    float* out = (float*)d_out;

    const int SMEM = 3*(128*64 + 64*64)*2;   // 73728
    static int grid = 0;
    if(!grid){
        cudaFuncSetAttribute(mega_k, cudaFuncAttributeMaxDynamicSharedMemorySize, SMEM);
        int nsm=0;
        cudaDeviceGetAttribute(&nsm, cudaDevAttrMultiProcessorCount, 0);
        int maxb=0;
        cudaOccupancyMaxActiveBlocksPerMultiprocessor(&maxb, mega_k, 256, SMEM);
        if(maxb<1) maxb=1;
        if(nsm<1)  nsm=1;
        grid = nsm*maxb;
    }

    mega_k<<<grid,256,SMEM>>>(input_ids, fc_W, fc_b, in_proj_W, conv_W, conv_b,
        x_proj_W, dt_proj_W, dt_proj_b, A_log, Dv, out_proj_W,
        norm_W, normf_W, head_W, out);
}

// round 8
// speedup vs baseline: 1.4337x; 1.0481x over previous
#include <cuda_runtime.h>
#include <cuda_fp16.h>
#include <math.h>
#include <stdint.h>

#define B_   4
#define L_   512
#define DM   384
#define NL   4
#define DI   768
#define NS   16
#define DTR  24
#define DC   4
#define VOCAB 1544
#define FEAT 1536
#define M_TOK (B_*L_)   // 2048 tokens
#define VPAD 1600

// ---------------- scratch (no allocations allowed) ----------------
__device__ float g_x[M_TOK*DM];
__device__ float g_xz[M_TOK*2*DI];
__device__ float g_u[M_TOK*DI];
__device__ float g_xdbl[M_TOK*(DTR+2*NS)];

__device__ __half g_ids16[M_TOK*VPAD];
__device__ __half g_fcW16[DM*VPAD];
__device__ __half g_inW16[NL*2*DI*DM];
__device__ __half g_xW16[NL*64*DI];
__device__ __half g_dtW16[NL*DI*64];
__device__ __half g_outW16[NL*DM*DI];
__device__ __half g_headW16[FEAT*DM];
__device__ __half g_h16[M_TOK*DM];
__device__ __half g_u16[M_TOK*DI];
__device__ __half g_y16[M_TOK*DI];
__device__ __half g_xdbl16[M_TOK*64];

__device__ __forceinline__ float sigmoidf_(float x){ return 1.f/(1.f+__expf(-x)); }
__device__ __forceinline__ float softplusf_(float v){
    return fmaxf(v,0.f)+log1pf(__expf(-fabsf(v)));
}
__device__ __forceinline__ uint32_t smem_u32(const void* p){
    uint32_t a;
    asm("{ .reg .u64 t; cvta.to.shared.u64 t, %1; cvt.u32.u64 %0, t; }" : "=r"(a) : "l"(p));
    return a;
}
__device__ __forceinline__ void cp16(uint32_t s, const void* g){
    asm volatile("cp.async.cg.shared.global [%0],[%1],16;"::"r"(s),"l"(g));
}
__device__ __forceinline__ void cp_commit(){ asm volatile("cp.async.commit_group;"); }
template<int N> __device__ __forceinline__ void cp_wait(){
    asm volatile("cp.async.wait_group %0;"::"n"(N));
}
__device__ __forceinline__ void ldsm_x4(uint32_t&r0,uint32_t&r1,uint32_t&r2,uint32_t&r3,uint32_t a){
    asm volatile("ldmatrix.sync.aligned.m8n8.x4.shared.b16 {%0,%1,%2,%3},[%4];"
        : "=r"(r0),"=r"(r1),"=r"(r2),"=r"(r3) : "r"(a));
}
__device__ __forceinline__ void mma16816(float&c0,float&c1,float&c2,float&c3,
    uint32_t a0,uint32_t a1,uint32_t a2,uint32_t a3,uint32_t b0,uint32_t b1){
    asm volatile("mma.sync.aligned.m16n8k16.row.col.f32.f16.f16.f32 "
        "{%0,%1,%2,%3},{%4,%5,%6,%7},{%8,%9},{%0,%1,%2,%3};"
        : "+f"(c0),"+f"(c1),"+f"(c2),"+f"(c3)
        : "r"(a0),"r"(a1),"r"(a2),"r"(a3),"r"(b0),"r"(b1));
}
__device__ __forceinline__ uint32_t swz(int row, int c16){
    return (uint32_t)(row*128 + (((c16)^(row&7))<<4));
}

// ============ HMMA f16 GEMM (3-stage cp.async): C = A @ W^T ==================
template<int MW,bool HAS_BIAS,bool SOFTPLUS,bool HAS_RES,bool WF16>
__global__ void __launch_bounds__(256) hgemm2(
    const __half* __restrict__ A, int lda, int nChunks,
    const __half* __restrict__ W, int ldw,
    const float* __restrict__ bias, const float* __restrict__ Res,
    float* __restrict__ C, int Nout, __half* __restrict__ C16, int ld16)
{
    constexpr int BM = MW*32;
    constexpr int NI = MW;
    constexpr int NWN = 8/MW;
    constexpr int A_STG = BM*64;
    constexpr int B_STG = 64*64;

    extern __shared__ __half smemh[];
    __half* sA = smemh;
    __half* sB = smemh + 3*A_STG;

    const int tid = threadIdx.x;
    const int w   = tid>>5, l = tid&31;
    const int wm  = w / NWN, wn = w % NWN;
    const int m0  = blockIdx.y*BM, n0 = blockIdx.x*64;

    const uint32_t sAb = smem_u32(sA), sBb = smem_u32(sB);
    const __half* Abase = A + (size_t)m0*lda;
    const __half* Wbase = W + (size_t)n0*ldw;

    float acc[2][NI][4];
    #pragma unroll
    for(int i=0;i<2;i++)
        #pragma unroll
        for(int j=0;j<NI;j++)
            #pragma unroll
            for(int q=0;q<4;q++) acc[i][j][q]=0.f;

    auto issue=[&](int c){
        const int st=c%3, k0=c*64;
        const uint32_t sa  = sAb + st*A_STG*2;
        const uint32_t sbp = sBb + st*B_STG*2;
        #pragma unroll
        for(int j=0;j<MW;j++){
            int g=tid+256*j, row=g>>3, c16=g&7;
            cp16(sa + swz(row,c16), Abase + (size_t)row*lda + k0 + c16*8);
        }
        #pragma unroll
        for(int j=0;j<2;j++){
            int g=tid+256*j, row=g>>3, c16=g&7;
            cp16(sbp + swz(row,c16), Wbase + (size_t)row*ldw + k0 + c16*8);
        }
        cp_commit();
    };

    issue(0);
    if(nChunks>1) issue(1);
    for(int c=0;c<nChunks;c++){
        if(c+2<nChunks){ issue(c+2); cp_wait<2>(); }
        else if(c+1<nChunks){ cp_wait<1>(); }
        else { cp_wait<0>(); }
        __syncthreads();
        const int st=c%3;
        const uint32_t aB = sAb + st*A_STG*2;
        const uint32_t bB = sBb + st*B_STG*2;
        #pragma unroll
        for(int ks=0;ks<4;ks++){
            uint32_t af[2][4];
            #pragma unroll
            for(int mi=0;mi<2;mi++){
                int row = wm*32 + mi*16 + (l&15);
                int c16 = ks*2 + (l>>4);
                ldsm_x4(af[mi][0],af[mi][1],af[mi][2],af[mi][3], aB + swz(row,c16));
            }
            uint32_t bf[NI][2];
            #pragma unroll
            for(int np=0;np<NI/2;np++){
                int row = wn*(8*MW) + np*16 + ((l>>4)<<3) + (l&7);
                int c16 = ks*2 + ((l>>3)&1);
                uint32_t r0,r1,r2,r3;
                ldsm_x4(r0,r1,r2,r3, bB + swz(row,c16));
                bf[np*2][0]=r0; bf[np*2][1]=r1; bf[np*2+1][0]=r2; bf[np*2+1][1]=r3;
            }
            #pragma unroll
            for(int mi=0;mi<2;mi++)
                #pragma unroll
                for(int ni=0;ni<NI;ni++)
                    mma16816(acc[mi][ni][0],acc[mi][ni][1],acc[mi][ni][2],acc[mi][ni][3],
                             af[mi][0],af[mi][1],af[mi][2],af[mi][3],
                             bf[ni][0],bf[ni][1]);
        }
        __syncthreads();
    }

    const int grp=l>>2, tig=l&3;
    #pragma unroll
    for(int mi=0;mi<2;mi++){
        int gm0 = m0 + wm*32 + mi*16 + grp;
        #pragma unroll
        for(int ni=0;ni<NI;ni++){
            int gn = n0 + wn*(8*MW) + ni*8 + tig*2;
            #pragma unroll
            for(int half=0; half<2; half++){
                int gm = gm0 + half*8;
                float v0=acc[mi][ni][half*2], v1=acc[mi][ni][half*2+1];
                if(gn<Nout){
                    if(HAS_BIAS){ v0+=bias[gn]; v1+=bias[gn+1]; }
                    if(SOFTPLUS){ v0=softplusf_(v0); v1=softplusf_(v1); }
                    if(HAS_RES){
                        v0 += Res[(size_t)gm*Nout+gn];
                        v1 += Res[(size_t)gm*Nout+gn+1];
                    }
                    C[(size_t)gm*Nout+gn]   = v0;
                    C[(size_t)gm*Nout+gn+1] = v1;
                }
                if(WF16){
                    if(gn<ld16){
                        __half2 hv = __floats2half2_rn(gn<Nout?v0:0.f, gn+1<Nout?v1:0.f);
                        *(__half2*)(C16 + (size_t)gm*ld16 + gn) = hv;
                    }
                }
            }
        }
    }
}

// ---------------- merged weight/input conversion ------------------
#define CR0 (M_TOK*VPAD)
#define CR1 (CR0 + DM*VPAD)
#define CR2 (CR1 + NL*2*DI*DM)
#define CR3 (CR2 + NL*64*DI)
#define CR4 (CR3 + NL*DI*64)
#define CR5 (CR4 + NL*DM*DI)
#define CR6 (CR5 + FEAT*DM)
__global__ __launch_bounds__(256) void cvt_all_k(
    const float* __restrict__ ids, const float* __restrict__ fcW,
    const float* __restrict__ inW, const float* __restrict__ xW,
    const float* __restrict__ dtW, const float* __restrict__ outW,
    const float* __restrict__ headW,
    __half* __restrict__ d_ids, __half* __restrict__ d_fcW,
    __half* __restrict__ d_inW, __half* __restrict__ d_xW,
    __half* __restrict__ d_dtW, __half* __restrict__ d_outW,
    __half* __restrict__ d_headW)
{
    int i=blockIdx.x*256+threadIdx.x;
    if(i<CR0){
        int r=i/VPAD, c=i%VPAD;
        d_ids[i]=__float2half(c<VOCAB ? ids[(size_t)r*VOCAB+c] : 0.f);
    } else if(i<CR1){
        int j=i-CR0, r=j/VPAD, c=j%VPAD;
        d_fcW[j]=__float2half(c<VOCAB ? fcW[(size_t)r*VOCAB+c] : 0.f);
    } else if(i<CR2){
        int j=i-CR1;
        d_inW[j]=__float2half(inW[j]);
    } else if(i<CR3){
        int j=i-CR2, lay=j/(64*DI), rem=j%(64*DI), r=rem/DI, cc=rem%DI;
        d_xW[j]=__float2half(r<DTR+2*NS ? xW[((size_t)lay*(DTR+2*NS)+r)*DI+cc] : 0.f);
    } else if(i<CR4){
        int j=i-CR3, row=j/64, c=j%64;
        d_dtW[j]=__float2half(c<DTR ? dtW[(size_t)row*DTR+c] : 0.f);
    } else if(i<CR5){
        int j=i-CR4;
        d_outW[j]=__float2half(outW[j]);
    } else if(i<CR6){
        int j=i-CR5;
        d_headW[j]=__float2half(headW[j]);
    }
}

// ---------------- RMSNorm -> f16 ----------------------------------
__global__ __launch_bounds__(128) void rmsnorm_k(
    const float* __restrict__ x, const float* __restrict__ w, __half* __restrict__ o)
{
    const int row=blockIdx.x, tid=threadIdx.x;
    float s=0.f;
    for(int c=tid;c<DM;c+=128){ float v=x[(size_t)row*DM+c]; s+=v*v; }
    #pragma unroll
    for(int off=16;off;off>>=1) s+=__shfl_xor_sync(0xffffffffu,s,off);
    __shared__ float ws[4];
    if((tid&31)==0) ws[tid>>5]=s;
    __syncthreads();
    if(tid<32){
        float t=(tid<4)?ws[tid]:0.f;
        t+=__shfl_xor_sync(0xffffffffu,t,1);
        t+=__shfl_xor_sync(0xffffffffu,t,2);
        if(tid==0) ws[0]=t;
    }
    __syncthreads();
    const float rms=rsqrtf(ws[0]/(float)DM + 1e-5f);
    for(int c=tid;c<DM;c+=128)
        o[(size_t)row*DM+c]=__float2half(x[(size_t)row*DM+c]*rms*w[c]);
}

// ---------------- depthwise causal conv(4) + SiLU -----------------
__global__ __launch_bounds__(256) void conv_silu_k(
    const float* __restrict__ xz, const float* __restrict__ cw,
    const float* __restrict__ cb, float* __restrict__ u, __half* __restrict__ u16)
{
    int idx=blockIdx.x*256+threadIdx.x;
    if(idx>=M_TOK*DI) return;
    int d=idx%DI, m=idx/DI, l=m%L_;
    float acc=cb[d];
    #pragma unroll
    for(int j=0;j<DC;j++){
        int ls=l-(DC-1)+j;
        if(ls>=0) acc=fmaf(xz[(size_t)(m-(DC-1)+j)*(2*DI)+d], cw[d*DC+j], acc);
    }
    float v=acc*sigmoidf_(acc);
    u[idx]=v;
    u16[idx]=__float2half(v);
}

// ---------------- scan (delta GEMM + softplus fused in) -----------
__global__ __launch_bounds__(128) void scan2_k(
    const __half* __restrict__ xdbl16, const __half* __restrict__ dtW16,
    const float* __restrict__ dtb,
    const float* __restrict__ u, const float* __restrict__ xdbl,
    const float* __restrict__ xz,
    const float* __restrict__ Alog, const float* __restrict__ Dv,
    __half* __restrict__ y)
{
    constexpr int CL=64, CPB=32;
    __shared__ float sB[CL][NS], sC[CL][NS];
    __shared__ float sd[CL][CPB], su[CL][CPB], sr[CL][CPB];
    __shared__ uint32_t sXd[CL][12];
    __shared__ __half sDtW[CPB][24];
    __shared__ float sdtb[CPB];

    const int b=blockIdx.y, ch0=blockIdx.x*CPB;
    const int tid=threadIdx.x, chl=tid>>2, sub=tid&3, ch=ch0+chl;

    for(int i=tid;i<CPB*24;i+=128) sDtW[i/24][i%24]=dtW16[(size_t)(ch0+i/24)*64 + i%24];
    if(tid<CPB) sdtb[tid]=dtb[ch0+tid];

    float a[4];
    #pragma unroll
    for(int j=0;j<4;j++) a[j]=-__expf(Alog[ch*NS + sub*4 + j]);
    const float Dd=Dv[ch];
    float h[4]={0.f,0.f,0.f,0.f};
    const int base=b*L_;

    for(int l0=0;l0<L_;l0+=CL){
        for(int i=tid;i<CL*32;i+=128){
            int s=i>>5, c=i&31;
            float v=xdbl[(size_t)(base+l0+s)*(DTR+2*NS) + DTR + c];
            if(c<NS) sB[s][c]=v; else sC[s][c-NS]=v;
        }
        for(int i=tid;i<CL*12;i+=128){
            int s=i/12, p=i%12;
            sXd[s][p]=((const uint32_t*)(xdbl16+(size_t)(base+l0+s)*64))[p];
        }
        for(int i=tid;i<CL*CPB;i+=128){
            int s=i/CPB, c=i%CPB;
            size_t row=(size_t)(base+l0+s);
            su[s][c]=u[row*DI+ch0+c];
            sr[s][c]=xz[row*(2*DI)+DI+ch0+c];
        }
        __syncthreads();
        for(int i=tid;i<CL*CPB;i+=128){
            int s=i>>5, c=i&31;
            float acc2=sdtb[c];
            #pragma unroll
            for(int p=0;p<12;p++){
                float2 xv=__half22float2(*(const __half2*)&sXd[s][p]);
                float2 wv=__half22float2(*(const __half2*)&sDtW[c][p*2]);
                acc2 = fmaf(xv.x,wv.x,fmaf(xv.y,wv.y,acc2));
            }
            sd[s][c]=softplusf_(acc2);
        }
        __syncthreads();
        #pragma unroll 4
        for(int s=0;s<CL;s++){
            float dt=sd[s][chl], ut=su[s][chl];
            float du=dt*ut;
            float acc2=0.f;
            #pragma unroll
            for(int j=0;j<4;j++){
                float dA=__expf(dt*a[j]);
                h[j]=fmaf(dA,h[j], du*sB[s][sub*4+j]);
                acc2=fmaf(h[j], sC[s][sub*4+j], acc2);
            }
            acc2+=__shfl_xor_sync(0xffffffffu,acc2,1);
            acc2+=__shfl_xor_sync(0xffffffffu,acc2,2);
            if(sub==0){
                float r=sr[s][chl];
                y[(size_t)(base+l0+s)*DI+ch]=__float2half((acc2+ut*Dd)*(r*sigmoidf_(r)));
            }
        }
        __syncthreads();
    }
}

// ---------------- host launcher -----------------------------------
extern "C" void kernel_launch(void* const* d_in, const int* in_sizes, int n_in,
                              void* d_out, int out_size)
{
    const float* input_ids = (const float*)d_in[0];
    const float* fc_W      = (const float*)d_in[1];
    const float* fc_b      = (const float*)d_in[2];
    const float* in_proj_W = (const float*)d_in[3];
    const float* conv_W    = (const float*)d_in[4];
    const float* conv_b    = (const float*)d_in[5];
    const float* x_proj_W  = (const float*)d_in[6];
    const float* dt_proj_W = (const float*)d_in[7];
    const float* dt_proj_b = (const float*)d_in[8];
    const float* A_log     = (const float*)d_in[9];
    const float* Dv        = (const float*)d_in[10];
    const float* out_proj_W= (const float*)d_in[11];
    const float* norm_W    = (const float*)d_in[12];
    const float* normf_W   = (const float*)d_in[13];
    const float* head_W    = (const float*)d_in[14];
    float* out = (float*)d_out;

    float *x,*xz,*u,*xdbl;
    __half *ids16,*fcW16,*inW16,*xW16,*dtW16,*outW16,*headW16,*h16,*u16,*y16,*xdbl16;
    cudaGetSymbolAddress((void**)&x,      g_x);
    cudaGetSymbolAddress((void**)&xz,     g_xz);
    cudaGetSymbolAddress((void**)&u,      g_u);
    cudaGetSymbolAddress((void**)&xdbl,   g_xdbl);
    cudaGetSymbolAddress((void**)&ids16,  g_ids16);
    cudaGetSymbolAddress((void**)&fcW16,  g_fcW16);
    cudaGetSymbolAddress((void**)&inW16,  g_inW16);
    cudaGetSymbolAddress((void**)&xW16,   g_xW16);
    cudaGetSymbolAddress((void**)&dtW16,  g_dtW16);
    cudaGetSymbolAddress((void**)&outW16, g_outW16);
    cudaGetSymbolAddress((void**)&headW16,g_headW16);
    cudaGetSymbolAddress((void**)&h16,    g_h16);
    cudaGetSymbolAddress((void**)&u16,    g_u16);
    cudaGetSymbolAddress((void**)&y16,    g_y16);
    cudaGetSymbolAddress((void**)&xdbl16, g_xdbl16);

    const int SM2 = 3*(64*64  + 64*64)*2;   // 49152
    const int SM4 = 3*(128*64 + 64*64)*2;   // 73728
    cudaFuncSetAttribute(hgemm2<2,true ,false,false,false>, cudaFuncAttributeMaxDynamicSharedMemorySize, SM2);
    cudaFuncSetAttribute(hgemm2<2,false,false,false,true >, cudaFuncAttributeMaxDynamicSharedMemorySize, SM2);
    cudaFuncSetAttribute(hgemm2<2,false,false,true ,false>, cudaFuncAttributeMaxDynamicSharedMemorySize, SM2);
    cudaFuncSetAttribute(hgemm2<4,false,false,false,false>, cudaFuncAttributeMaxDynamicSharedMemorySize, SM4);

    // 1. all conversions in one kernel
    cvt_all_k<<<(CR6+255)/256,256>>>(input_ids, fc_W, in_proj_W, x_proj_W,
        dt_proj_W, out_proj_W, head_W,
        ids16, fcW16, inW16, xW16, dtW16, outW16, headW16);

    // 2. fc: x = ids @ fc_W^T + b  (K=1600, 25 chunks), 192 blocks
    hgemm2<2,true,false,false,false><<<dim3(6,32),256,SM2>>>(
        ids16, VPAD, 25, fcW16, VPAD, fc_b, nullptr, x, DM, nullptr, 0);

    for(int i=0;i<NL;i++){
        rmsnorm_k<<<M_TOK,128>>>(x, norm_W+(size_t)i*DM, h16);
        // xz = h @ in_proj^T  (K=384, 6 chunks), 384 blocks
        hgemm2<4,false,false,false,false><<<dim3(24,16),256,SM4>>>(
            h16, DM, 6, inW16+(size_t)i*2*DI*DM, DM, nullptr, nullptr, xz, 2*DI, nullptr, 0);
        conv_silu_k<<<(M_TOK*DI+255)/256,256>>>(xz, conv_W+(size_t)i*DI*DC,
                                                conv_b+(size_t)i*DI, u, u16);
        // x_dbl = u @ x_proj^T  (K=768, 12 chunks), 32 blocks; dual f32+f16 out
        hgemm2<2,false,false,false,true><<<dim3(1,32),256,SM2>>>(
            u16, DI, 12, xW16+(size_t)i*64*DI, DI, nullptr, nullptr,
            xdbl, DTR+2*NS, xdbl16, 64);
        // scan with fused delta-GEMM + softplus
        scan2_k<<<dim3(DI/32, B_),128>>>(
            xdbl16, dtW16+(size_t)i*DI*64, dt_proj_b+(size_t)i*DI,
            u, xdbl, xz, A_log+(size_t)i*DI*NS, Dv+(size_t)i*DI, y16);
        // x = y @ out_proj^T + x  (K=768, 12 chunks), 192 blocks
        hgemm2<2,false,false,true,false><<<dim3(6,32),256,SM2>>>(
            y16, DI, 12, outW16+(size_t)i*DM*DI, DI, nullptr, x, x, DM, nullptr, 0);
    }

    rmsnorm_k<<<M_TOK,128>>>(x, normf_W, h16);
    // out = h @ head^T  (K=384, 6 chunks), 384 blocks
    hgemm2<4,false,false,false,false><<<dim3(24,16),256,SM4>>>(
        h16, DM, 6, headW16, DM, nullptr, nullptr, out, FEAT, nullptr, 0);
}

// round 9
// speedup vs baseline: 1.6123x; 1.1245x over previous
#include <cuda_runtime.h>
#include <cuda_fp16.h>
#include <math.h>
#include <stdint.h>

#define B_   4
#define L_   512
#define DM   384
#define NL   4
#define DI   768
#define NS   16
#define DTR  24
#define DC   4
#define VOCAB 1544
#define FEAT 1536
#define M_TOK (B_*L_)   // 2048 tokens
#define VPAD 1600

// ---------------- scratch (no allocations allowed) ----------------
__device__ float g_x[M_TOK*DM];
__device__ float g_xz[M_TOK*2*DI];
__device__ float g_u[M_TOK*DI];
__device__ float g_xdbl[M_TOK*(DTR+2*NS)];
__device__ float g_delta[M_TOK*DI];

__device__ __half g_ids16[M_TOK*VPAD];
__device__ __half g_fcW16[DM*VPAD];
__device__ __half g_inW16[NL*2*DI*DM];
__device__ __half g_xW16[NL*64*DI];
__device__ __half g_dtW16[NL*DI*64];
__device__ __half g_outW16[NL*DM*DI];
__device__ __half g_headW16[FEAT*DM];
__device__ __half g_h16[M_TOK*DM];
__device__ __half g_u16[M_TOK*DI];
__device__ __half g_y16[M_TOK*DI];
__device__ __half g_xdbl16[M_TOK*64];

__device__ __forceinline__ float sigmoidf_(float x){ return 1.f/(1.f+__expf(-x)); }
__device__ __forceinline__ float softplusf_(float v){
    return fmaxf(v,0.f)+log1pf(__expf(-fabsf(v)));
}
__device__ __forceinline__ uint32_t smem_u32(const void* p){
    uint32_t a;
    asm("{ .reg .u64 t; cvta.to.shared.u64 t, %1; cvt.u32.u64 %0, t; }" : "=r"(a) : "l"(p));
    return a;
}
__device__ __forceinline__ void cp16(uint32_t s, const void* g){
    asm volatile("cp.async.cg.shared.global [%0],[%1],16;"::"r"(s),"l"(g));
}
__device__ __forceinline__ void cp_commit(){ asm volatile("cp.async.commit_group;"); }
template<int N> __device__ __forceinline__ void cp_wait(){
    asm volatile("cp.async.wait_group %0;"::"n"(N));
}
__device__ __forceinline__ void ldsm_x4(uint32_t&r0,uint32_t&r1,uint32_t&r2,uint32_t&r3,uint32_t a){
    asm volatile("ldmatrix.sync.aligned.m8n8.x4.shared.b16 {%0,%1,%2,%3},[%4];"
        : "=r"(r0),"=r"(r1),"=r"(r2),"=r"(r3) : "r"(a));
}
__device__ __forceinline__ void mma16816(float&c0,float&c1,float&c2,float&c3,
    uint32_t a0,uint32_t a1,uint32_t a2,uint32_t a3,uint32_t b0,uint32_t b1){
    asm volatile("mma.sync.aligned.m16n8k16.row.col.f32.f16.f16.f32 "
        "{%0,%1,%2,%3},{%4,%5,%6,%7},{%8,%9},{%0,%1,%2,%3};"
        : "+f"(c0),"+f"(c1),"+f"(c2),"+f"(c3)
        : "r"(a0),"r"(a1),"r"(a2),"r"(a3),"r"(b0),"r"(b1));
}
__device__ __forceinline__ uint32_t swz(int row, int c16){
    return (uint32_t)(row*128 + (((c16)^(row&7))<<4));
}

// ============ HMMA f16 GEMM (4-stage cp.async, 1 sync/chunk) =================
// ordering per chunk: wait(group c) -> syncthreads -> issue(c+3) -> compute(c)
// barrier guarantees no warp writes stage (c+3)%4 while any warp reads stage c%4.
template<int MW,bool HAS_BIAS,bool SOFTPLUS,bool HAS_RES,bool WF16>
__global__ void __launch_bounds__(256) hgemm2(
    const __half* __restrict__ A, int lda, int nChunks,
    const __half* __restrict__ W, int ldw,
    const float* __restrict__ bias, const float* __restrict__ Res,
    float* __restrict__ C, int Nout, __half* __restrict__ C16, int ld16)
{
    constexpr int BM = MW*32;
    constexpr int NI = MW;
    constexpr int NWN = 8/MW;
    constexpr int A_STG = BM*64;
    constexpr int B_STG = 64*64;

    extern __shared__ __half smemh[];
    __half* sA = smemh;
    __half* sB = smemh + 4*A_STG;

    const int tid = threadIdx.x;
    const int w   = tid>>5, l = tid&31;
    const int wm  = w / NWN, wn = w % NWN;
    const int m0  = blockIdx.y*BM, n0 = blockIdx.x*64;

    const uint32_t sAb = smem_u32(sA), sBb = smem_u32(sB);
    const __half* Abase = A + (size_t)m0*lda;
    const __half* Wbase = W + (size_t)n0*ldw;

    float acc[2][NI][4];
    #pragma unroll
    for(int i=0;i<2;i++)
        #pragma unroll
        for(int j=0;j<NI;j++)
            #pragma unroll
            for(int q=0;q<4;q++) acc[i][j][q]=0.f;

    auto issue=[&](int c){
        const int st=c&3, k0=c*64;
        const uint32_t sa  = sAb + st*A_STG*2;
        const uint32_t sbp = sBb + st*B_STG*2;
        #pragma unroll
        for(int j=0;j<MW;j++){
            int g=tid+256*j, row=g>>3, c16=g&7;
            cp16(sa + swz(row,c16), Abase + (size_t)row*lda + k0 + c16*8);
        }
        #pragma unroll
        for(int j=0;j<2;j++){
            int g=tid+256*j, row=g>>3, c16=g&7;
            cp16(sbp + swz(row,c16), Wbase + (size_t)row*ldw + k0 + c16*8);
        }
        cp_commit();
    };

    issue(0);
    if(nChunks>1) issue(1);
    if(nChunks>2) issue(2);
    for(int c=0;c<nChunks;c++){
        const int rem = nChunks-1-c;
        if(rem>=2)      cp_wait<2>();
        else if(rem==1) cp_wait<1>();
        else            cp_wait<0>();
        __syncthreads();
        if(c+3<nChunks) issue(c+3);
        const int st=c&3;
        const uint32_t aB = sAb + st*A_STG*2;
        const uint32_t bB = sBb + st*B_STG*2;
        #pragma unroll
        for(int ks=0;ks<4;ks++){
            uint32_t af[2][4];
            #pragma unroll
            for(int mi=0;mi<2;mi++){
                int row = wm*32 + mi*16 + (l&15);
                int c16 = ks*2 + (l>>4);
                ldsm_x4(af[mi][0],af[mi][1],af[mi][2],af[mi][3], aB + swz(row,c16));
            }
            uint32_t bf[NI][2];
            #pragma unroll
            for(int np=0;np<NI/2;np++){
                int row = wn*(8*MW) + np*16 + ((l>>4)<<3) + (l&7);
                int c16 = ks*2 + ((l>>3)&1);
                uint32_t r0,r1,r2,r3;
                ldsm_x4(r0,r1,r2,r3, bB + swz(row,c16));
                bf[np*2][0]=r0; bf[np*2][1]=r1; bf[np*2+1][0]=r2; bf[np*2+1][1]=r3;
            }
            #pragma unroll
            for(int mi=0;mi<2;mi++)
                #pragma unroll
                for(int ni=0;ni<NI;ni++)
                    mma16816(acc[mi][ni][0],acc[mi][ni][1],acc[mi][ni][2],acc[mi][ni][3],
                             af[mi][0],af[mi][1],af[mi][2],af[mi][3],
                             bf[ni][0],bf[ni][1]);
        }
    }

    const int grp=l>>2, tig=l&3;
    #pragma unroll
    for(int mi=0;mi<2;mi++){
        int gm0 = m0 + wm*32 + mi*16 + grp;
        #pragma unroll
        for(int ni=0;ni<NI;ni++){
            int gn = n0 + wn*(8*MW) + ni*8 + tig*2;
            #pragma unroll
            for(int half=0; half<2; half++){
                int gm = gm0 + half*8;
                float v0=acc[mi][ni][half*2], v1=acc[mi][ni][half*2+1];
                if(gn<Nout){
                    if(HAS_BIAS){ v0+=bias[gn]; v1+=bias[gn+1]; }
                    if(SOFTPLUS){ v0=softplusf_(v0); v1=softplusf_(v1); }
                    if(HAS_RES){
                        v0 += Res[(size_t)gm*Nout+gn];
                        v1 += Res[(size_t)gm*Nout+gn+1];
                    }
                    C[(size_t)gm*Nout+gn]   = v0;
                    C[(size_t)gm*Nout+gn+1] = v1;
                }
                if(WF16){
                    if(gn<ld16){
                        __half2 hv = __floats2half2_rn(gn<Nout?v0:0.f, gn+1<Nout?v1:0.f);
                        *(__half2*)(C16 + (size_t)gm*ld16 + gn) = hv;
                    }
                }
            }
        }
    }
}

// ---------------- merged weight/input conversion ------------------
#define CR0 (M_TOK*VPAD)
#define CR1 (CR0 + DM*VPAD)
#define CR2 (CR1 + NL*2*DI*DM)
#define CR3 (CR2 + NL*64*DI)
#define CR4 (CR3 + NL*DI*64)
#define CR5 (CR4 + NL*DM*DI)
#define CR6 (CR5 + FEAT*DM)
__global__ __launch_bounds__(256) void cvt_all_k(
    const float* __restrict__ ids, const float* __restrict__ fcW,
    const float* __restrict__ inW, const float* __restrict__ xW,
    const float* __restrict__ dtW, const float* __restrict__ outW,
    const float* __restrict__ headW,
    __half* __restrict__ d_ids, __half* __restrict__ d_fcW,
    __half* __restrict__ d_inW, __half* __restrict__ d_xW,
    __half* __restrict__ d_dtW, __half* __restrict__ d_outW,
    __half* __restrict__ d_headW)
{
    int i=blockIdx.x*256+threadIdx.x;
    if(i<CR0){
        int r=i/VPAD, c=i%VPAD;
        d_ids[i]=__float2half(c<VOCAB ? ids[(size_t)r*VOCAB+c] : 0.f);
    } else if(i<CR1){
        int j=i-CR0, r=j/VPAD, c=j%VPAD;
        d_fcW[j]=__float2half(c<VOCAB ? fcW[(size_t)r*VOCAB+c] : 0.f);
    } else if(i<CR2){
        int j=i-CR1;
        d_inW[j]=__float2half(inW[j]);
    } else if(i<CR3){
        int j=i-CR2, lay=j/(64*DI), rem=j%(64*DI), r=rem/DI, cc=rem%DI;
        d_xW[j]=__float2half(r<DTR+2*NS ? xW[((size_t)lay*(DTR+2*NS)+r)*DI+cc] : 0.f);
    } else if(i<CR4){
        int j=i-CR3, row=j/64, c=j%64;
        d_dtW[j]=__float2half(c<DTR ? dtW[(size_t)row*DTR+c] : 0.f);
    } else if(i<CR5){
        int j=i-CR4;
        d_outW[j]=__float2half(outW[j]);
    } else if(i<CR6){
        int j=i-CR5;
        d_headW[j]=__float2half(headW[j]);
    }
}

// ---------------- RMSNorm (warp per row) -> f16 -------------------
__global__ __launch_bounds__(256) void rmsnorm_k(
    const float* __restrict__ x, const float* __restrict__ w, __half* __restrict__ o)
{
    const int lane=threadIdx.x&31;
    const int row = blockIdx.x*8 + (threadIdx.x>>5);
    float s=0.f, v[12];
    #pragma unroll
    for(int j=0;j<12;j++){ v[j]=x[(size_t)row*DM + lane + 32*j]; s+=v[j]*v[j]; }
    #pragma unroll
    for(int off=16;off;off>>=1) s+=__shfl_xor_sync(0xffffffffu,s,off);
    const float rms=rsqrtf(s/(float)DM + 1e-5f);
    #pragma unroll
    for(int j=0;j<12;j++)
        o[(size_t)row*DM + lane + 32*j]=__float2half(v[j]*rms*w[lane+32*j]);
}

// ---------------- depthwise causal conv(4) + SiLU (x4 vec) --------
__global__ __launch_bounds__(256) void conv_silu_k(
    const float* __restrict__ xz, const float* __restrict__ cw,
    const float* __restrict__ cb, float* __restrict__ u, __half* __restrict__ u16)
{
    int idx=blockIdx.x*256+threadIdx.x;      // over M_TOK*DI/4
    if(idx>=M_TOK*DI/4) return;
    int m=idx/(DI/4), q=idx%(DI/4), d0=q*4, l=m%L_;
    float4 cw4[4];
    #pragma unroll
    for(int c=0;c<4;c++) cw4[c]=*(const float4*)&cw[(d0+c)*DC];
    float4 acc=*(const float4*)&cb[d0];
    #pragma unroll
    for(int j=0;j<DC;j++){
        int ls=l-(DC-1)+j;
        if(ls>=0){
            float4 v=*(const float4*)&xz[(size_t)(m-(DC-1)+j)*(2*DI)+d0];
            acc.x=fmaf(v.x,((const float*)&cw4[0])[j],acc.x);
            acc.y=fmaf(v.y,((const float*)&cw4[1])[j],acc.y);
            acc.z=fmaf(v.z,((const float*)&cw4[2])[j],acc.z);
            acc.w=fmaf(v.w,((const float*)&cw4[3])[j],acc.w);
        }
    }
    float4 r;
    r.x=acc.x*sigmoidf_(acc.x); r.y=acc.y*sigmoidf_(acc.y);
    r.z=acc.z*sigmoidf_(acc.z); r.w=acc.w*sigmoidf_(acc.w);
    *(float4*)&u[(size_t)m*DI+d0]=r;
    __half2 h0=__floats2half2_rn(r.x,r.y), h1=__floats2half2_rn(r.z,r.w);
    *(__half2*)&u16[(size_t)m*DI+d0]=h0;
    *(__half2*)&u16[(size_t)m*DI+d0+2]=h1;
}

// ---------------- selective scan (R5 version, proven) -------------
__global__ __launch_bounds__(128) void scan_k(
    const float* __restrict__ delta, const float* __restrict__ u,
    const float* __restrict__ xdbl,  const float* __restrict__ xz,
    const float* __restrict__ Alog,  const float* __restrict__ Dv,
    __half* __restrict__ y)
{
    constexpr int CL=64, CPB=32;
    __shared__ float sB[CL][NS], sC[CL][NS];
    __shared__ float sd[CL][CPB], su[CL][CPB], sr[CL][CPB];

    const int b=blockIdx.y, ch0=blockIdx.x*CPB;
    const int tid=threadIdx.x, chl=tid>>2, sub=tid&3, ch=ch0+chl;

    float a[4];
    #pragma unroll
    for(int j=0;j<4;j++) a[j]=-__expf(Alog[ch*NS + sub*4 + j]);
    const float Dd=Dv[ch];
    float h[4]={0.f,0.f,0.f,0.f};
    const int base=b*L_;

    for(int l0=0;l0<L_;l0+=CL){
        for(int i=tid;i<CL*32;i+=128){
            int s=i>>5, c=i&31;
            float v=xdbl[(size_t)(base+l0+s)*(DTR+2*NS) + DTR + c];
            if(c<NS) sB[s][c]=v; else sC[s][c-NS]=v;
        }
        for(int i=tid;i<CL*CPB;i+=128){
            int s=i/CPB, c=i%CPB;
            size_t row=(size_t)(base+l0+s);
            sd[s][c]=delta[row*DI+ch0+c];
            su[s][c]=u[row*DI+ch0+c];
            sr[s][c]=xz[row*(2*DI)+DI+ch0+c];
        }
        __syncthreads();
        #pragma unroll 4
        for(int s=0;s<CL;s++){
            float dt=sd[s][chl], ut=su[s][chl];
            float du=dt*ut;
            float acc=0.f;
            #pragma unroll
            for(int j=0;j<4;j++){
                float dA=__expf(dt*a[j]);
                h[j]=fmaf(dA,h[j], du*sB[s][sub*4+j]);
                acc=fmaf(h[j], sC[s][sub*4+j], acc);
            }
            acc+=__shfl_xor_sync(0xffffffffu,acc,1);
            acc+=__shfl_xor_sync(0xffffffffu,acc,2);
            if(sub==0){
                float r=sr[s][chl];
                y[(size_t)(base+l0+s)*DI+ch]=__float2half((acc+ut*Dd)*(r*sigmoidf_(r)));
            }
        }
        __syncthreads();
    }
}

// ---------------- host launcher -----------------------------------
extern "C" void kernel_launch(void* const* d_in, const int* in_sizes, int n_in,
                              void* d_out, int out_size)
{
    const float* input_ids = (const float*)d_in[0];
    const float* fc_W      = (const float*)d_in[1];
    const float* fc_b      = (const float*)d_in[2];
    const float* in_proj_W = (const float*)d_in[3];
    const float* conv_W    = (const float*)d_in[4];
    const float* conv_b    = (const float*)d_in[5];
    const float* x_proj_W  = (const float*)d_in[6];
    const float* dt_proj_W = (const float*)d_in[7];
    const float* dt_proj_b = (const float*)d_in[8];
    const float* A_log     = (const float*)d_in[9];
    const float* Dv        = (const float*)d_in[10];
    const float* out_proj_W= (const float*)d_in[11];
    const float* norm_W    = (const float*)d_in[12];
    const float* normf_W   = (const float*)d_in[13];
    const float* head_W    = (const float*)d_in[14];
    float* out = (float*)d_out;

    float *x,*xz,*u,*xdbl,*delta;
    __half *ids16,*fcW16,*inW16,*xW16,*dtW16,*outW16,*headW16,*h16,*u16,*y16,*xdbl16;
    cudaGetSymbolAddress((void**)&x,      g_x);
    cudaGetSymbolAddress((void**)&xz,     g_xz);
    cudaGetSymbolAddress((void**)&u,      g_u);
    cudaGetSymbolAddress((void**)&xdbl,   g_xdbl);
    cudaGetSymbolAddress((void**)&delta,  g_delta);
    cudaGetSymbolAddress((void**)&ids16,  g_ids16);
    cudaGetSymbolAddress((void**)&fcW16,  g_fcW16);
    cudaGetSymbolAddress((void**)&inW16,  g_inW16);
    cudaGetSymbolAddress((void**)&xW16,   g_xW16);
    cudaGetSymbolAddress((void**)&dtW16,  g_dtW16);
    cudaGetSymbolAddress((void**)&outW16, g_outW16);
    cudaGetSymbolAddress((void**)&headW16,g_headW16);
    cudaGetSymbolAddress((void**)&h16,    g_h16);
    cudaGetSymbolAddress((void**)&u16,    g_u16);
    cudaGetSymbolAddress((void**)&y16,    g_y16);
    cudaGetSymbolAddress((void**)&xdbl16, g_xdbl16);

    const int SM2 = 4*(64*64  + 64*64)*2;   // 65536
    const int SM4 = 4*(128*64 + 64*64)*2;   // 98304
    cudaFuncSetAttribute(hgemm2<2,true ,false,false,false>, cudaFuncAttributeMaxDynamicSharedMemorySize, SM2);
    cudaFuncSetAttribute(hgemm2<2,false,false,false,true >, cudaFuncAttributeMaxDynamicSharedMemorySize, SM2);
    cudaFuncSetAttribute(hgemm2<2,false,false,true ,false>, cudaFuncAttributeMaxDynamicSharedMemorySize, SM2);
    cudaFuncSetAttribute(hgemm2<4,false,false,false,false>, cudaFuncAttributeMaxDynamicSharedMemorySize, SM4);
    cudaFuncSetAttribute(hgemm2<4,true ,true ,false,false>, cudaFuncAttributeMaxDynamicSharedMemorySize, SM4);

    // 1. all conversions, one kernel
    cvt_all_k<<<(CR6+255)/256,256>>>(input_ids, fc_W, in_proj_W, x_proj_W,
        dt_proj_W, out_proj_W, head_W,
        ids16, fcW16, inW16, xW16, dtW16, outW16, headW16);

    // 2. fc: x = ids @ fc_W^T + b  (K=1600, 25 chunks), 192 blocks
    hgemm2<2,true,false,false,false><<<dim3(6,32),256,SM2>>>(
        ids16, VPAD, 25, fcW16, VPAD, fc_b, nullptr, x, DM, nullptr, 0);

    for(int i=0;i<NL;i++){
        rmsnorm_k<<<M_TOK/8,256>>>(x, norm_W+(size_t)i*DM, h16);
        // xz = h @ in_proj^T  (K=384, 6 chunks), 384 blocks
        hgemm2<4,false,false,false,false><<<dim3(24,16),256,SM4>>>(
            h16, DM, 6, inW16+(size_t)i*2*DI*DM, DM, nullptr, nullptr, xz, 2*DI, nullptr, 0);
        conv_silu_k<<<(M_TOK*DI/4+255)/256,256>>>(xz, conv_W+(size_t)i*DI*DC,
                                                  conv_b+(size_t)i*DI, u, u16);
        // x_dbl = u @ x_proj^T  (K=768, 12 chunks), 32 blocks; dual f32+f16 out
        hgemm2<2,false,false,false,true><<<dim3(1,32),256,SM2>>>(
            u16, DI, 12, xW16+(size_t)i*64*DI, DI, nullptr, nullptr,
            xdbl, DTR+2*NS, xdbl16, 64);
        // delta = softplus(xdbl16 @ dtW16^T + b)  (K=64, 1 chunk), 192 blocks
        hgemm2<4,true,true,false,false><<<dim3(12,16),256,SM4>>>(
            xdbl16, 64, 1, dtW16+(size_t)i*DI*64, 64,
            dt_proj_b+(size_t)i*DI, nullptr, delta, DI, nullptr, 0);
        scan_k<<<dim3(DI/32, B_),128>>>(delta, u, xdbl, xz,
                                        A_log+(size_t)i*DI*NS, Dv+(size_t)i*DI, y16);
        // x = y @ out_proj^T + x  (K=768, 12 chunks), 192 blocks
        hgemm2<2,false,false,true,false><<<dim3(6,32),256,SM2>>>(
            y16, DI, 12, outW16+(size_t)i*DM*DI, DI, nullptr, x, x, DM, nullptr, 0);
    }

    rmsnorm_k<<<M_TOK/8,256>>>(x, normf_W, h16);
    // out = h @ head^T  (K=384, 6 chunks), 384 blocks
    hgemm2<4,false,false,false,false><<<dim3(24,16),256,SM4>>>(
        h16, DM, 6, headW16, DM, nullptr, nullptr, out, FEAT, nullptr, 0);
}